// round 3
// baseline (speedup 1.0000x reference)
#include <cuda_runtime.h>

namespace {

constexpr int kNodes = 50000;
constexpr int kEdges = 800000;
constexpr int kD     = 128;   // 8 capsules x 16 dims

// Scratch state (allocation-free: __device__ globals). float4-typed => 16B aligned.
__device__ float4 g_xc [kNodes * 32];  // per-capsule-normalized input
__device__ float4 g_u  [kNodes * 32];  // current routing state
__device__ float4 g_acc[kNodes * 32];  // segment-sum accumulator (kept zeroed)
__device__ int    g_is_i32;            // 1 if edge_index is int32, 0 if int64

__device__ __forceinline__ float group4_sum(float v) {
    v += __shfl_xor_sync(0xffffffffu, v, 1);
    v += __shfl_xor_sync(0xffffffffu, v, 2);
    return v;
}

// Detect edge_index dtype: int64 nonneg values < 2^31 have zero high words.
__global__ void detect_kernel(const unsigned int* __restrict__ w) {
    unsigned int acc = 0;
    for (int i = threadIdx.x; i < 1024; i += 32) acc |= w[2 * i + 1];
    acc |= __shfl_xor_sync(0xffffffffu, acc, 1);
    acc |= __shfl_xor_sync(0xffffffffu, acc, 2);
    acc |= __shfl_xor_sync(0xffffffffu, acc, 4);
    acc |= __shfl_xor_sync(0xffffffffu, acc, 8);
    acc |= __shfl_xor_sync(0xffffffffu, acc, 16);
    if (threadIdx.x == 0) g_is_i32 = (acc != 0) ? 1 : 0;
}

// xc = l2norm_per_capsule(x); u = xc; acc = 0.  One warp per node, float4/lane.
__global__ void __launch_bounds__(256) init_kernel(const float* __restrict__ x) {
    int gid  = blockIdx.x * blockDim.x + threadIdx.x;
    int node = gid >> 5;
    if (node >= kNodes) return;
    int t   = gid & 31;
    int idx = node * 32 + t;

    float4 v = reinterpret_cast<const float4*>(x)[idx];
    float ss = group4_sum(v.x * v.x + v.y * v.y + v.z * v.z + v.w * v.w);
    float s  = 1.0f / fmaxf(sqrtf(ss), 1e-12f);
    v.x *= s; v.y *= s; v.z *= s; v.w *= s;

    g_xc[idx]  = v;
    g_u[idx]   = v;
    g_acc[idx] = make_float4(0.f, 0.f, 0.f, 0.f);
}

// One warp per edge. Lane t handles float4 #t of the 128-float row.
// Capsule of lane t = t>>2 (4 lanes per capsule).
__global__ void __launch_bounds__(256) edge_kernel(const void* __restrict__ ei) {
    int gid = blockIdx.x * blockDim.x + threadIdx.x;
    int e   = gid >> 5;
    if (e >= kEdges) return;
    int t = gid & 31;

    int s, g;
    if (g_is_i32) {
        const int* p = (const int*)ei;
        s = __ldg(p + e);
        g = __ldg(p + kEdges + e);
    } else {
        const long long* p = (const long long*)ei;
        s = (int)__ldg(p + e);
        g = (int)__ldg(p + kEdges + e);
    }

    float4 z = g_xc[s * 32 + t];
    float4 u = g_u [g * 32 + t];

    // Per-capsule agreement p[c] = <z_c, u_c>  (16-dim dot = group-of-4 reduce)
    float p = group4_sum(z.x * u.x + z.y * u.y + z.z * u.z + z.w * u.w);

    // Softmax over the 8 capsules (TAU = 1). All 4 lanes of a capsule hold the
    // same p, so xor{4,8,16} reduces across capsules correctly for every lane.
    float m = p;
    m = fmaxf(m, __shfl_xor_sync(0xffffffffu, m, 4));
    m = fmaxf(m, __shfl_xor_sync(0xffffffffu, m, 8));
    m = fmaxf(m, __shfl_xor_sync(0xffffffffu, m, 16));
    float ex = __expf(p - m);
    float sum = ex;
    sum += __shfl_xor_sync(0xffffffffu, sum, 4);
    sum += __shfl_xor_sync(0xffffffffu, sum, 8);
    sum += __shfl_xor_sync(0xffffffffu, sum, 16);
    float w = __fdividef(ex, sum);

    // acc[trg] += z * w   (vector reduction: 1 red.v4 per lane, no return trip)
    float4* dst = g_acc + g * 32 + t;
    asm volatile("red.global.add.v4.f32 [%0], {%1, %2, %3, %4};"
                 :: "l"(dst), "f"(z.x * w), "f"(z.y * w), "f"(z.z * w), "f"(z.w * w)
                 : "memory");
}

// u = l2norm_per_capsule(acc + xc); acc = 0.  WRITE_OUT selects final dest.
template <bool WRITE_OUT>
__global__ void __launch_bounds__(256) node_kernel(float* __restrict__ out) {
    int gid  = blockIdx.x * blockDim.x + threadIdx.x;
    int node = gid >> 5;
    if (node >= kNodes) return;
    int t   = gid & 31;
    int idx = node * 32 + t;

    float4 a = g_acc[idx];
    float4 c = g_xc[idx];
    float4 v = make_float4(a.x + c.x, a.y + c.y, a.z + c.z, a.w + c.w);

    float ss = group4_sum(v.x * v.x + v.y * v.y + v.z * v.z + v.w * v.w);
    float s  = 1.0f / fmaxf(sqrtf(ss), 1e-12f);
    v.x *= s; v.y *= s; v.z *= s; v.w *= s;

    if (WRITE_OUT) {
        reinterpret_cast<float4*>(out)[idx] = v;
    } else {
        g_u[idx] = v;
    }
    // Re-zero accumulator for the next edge pass / next graph replay.
    g_acc[idx] = make_float4(0.f, 0.f, 0.f, 0.f);
}

}  // namespace

extern "C" void kernel_launch(void* const* d_in, const int* in_sizes, int n_in,
                              void* d_out, int out_size) {
    const float* x  = (const float*)d_in[0];
    const void*  ei = d_in[1];   // [2, E], int32 or int64 (detected on-device)
    float* out = (float*)d_out;

    const int nodeBlocks = (kNodes * 32 + 255) / 256;
    const int edgeBlocks = (kEdges * 32 + 255) / 256;

    detect_kernel<<<1, 32>>>((const unsigned int*)ei);
    init_kernel<<<nodeBlocks, 256>>>(x);
    for (int it = 0; it < 3; ++it) {
        edge_kernel<<<edgeBlocks, 256>>>(ei);
        if (it < 2) {
            node_kernel<false><<<nodeBlocks, 256>>>(nullptr);
        } else {
            node_kernel<true><<<nodeBlocks, 256>>>(out);
        }
    }
}

// round 4
// speedup vs baseline: 1.0691x; 1.0691x over previous
#include <cuda_runtime.h>

namespace {

constexpr int kNodes = 50000;
constexpr int kEdges = 800000;

// Scratch (allocation-free __device__ globals; float4-typed => 16B aligned).
__device__ float4 g_xc[kNodes * 32];   // per-capsule-normalized input
__device__ float4 g_u [kNodes * 32];   // routing state (updated in place per node)
__device__ int    g_count [kNodes + 1];
__device__ int    g_offs  [kNodes + 1];  // CSR row offsets (by target)
__device__ int    g_cursor[kNodes + 1];
__device__ int    g_srcs  [kEdges];      // CSR column (source node per edge)
__device__ int    g_is_i32;              // edge_index dtype flag

__device__ __forceinline__ float group4_sum(float v) {
    v += __shfl_xor_sync(0xffffffffu, v, 1);
    v += __shfl_xor_sync(0xffffffffu, v, 2);
    return v;
}

__device__ __forceinline__ int load_idx(const void* ei, long long off) {
    if (g_is_i32) return ((const int*)ei)[off];
    return (int)((const long long*)ei)[off];
}

// ---- preprocessing: dtype detect + counting sort of edges by target ----

__global__ void detect_kernel(const unsigned int* __restrict__ w) {
    unsigned int acc = 0;
    for (int i = threadIdx.x; i < 1024; i += 32) acc |= w[2 * i + 1];
    #pragma unroll
    for (int d = 1; d < 32; d <<= 1) acc |= __shfl_xor_sync(0xffffffffu, acc, d);
    if (threadIdx.x == 0) g_is_i32 = (acc != 0) ? 1 : 0;
}

__global__ void zero_count_kernel() {
    int i = blockIdx.x * blockDim.x + threadIdx.x;
    if (i <= kNodes) g_count[i] = 0;
}

__global__ void hist_kernel(const void* __restrict__ ei) {
    int e = blockIdx.x * blockDim.x + threadIdx.x;
    if (e >= kEdges) return;
    atomicAdd(&g_count[load_idx(ei, (long long)kEdges + e)], 1);
}

// Single-block exclusive scan over 50000 counts (1024 threads x 49 chunk).
__global__ void scan_kernel() {
    __shared__ int sh[1024];
    const int T = 1024, C = (kNodes + 1023) / 1024;  // 49
    int t = threadIdx.x;

    int sum = 0;
    for (int k = 0; k < C; ++k) {
        int i = t * C + k;
        if (i < kNodes) sum += g_count[i];
    }
    sh[t] = sum;
    __syncthreads();
    for (int off = 1; off < T; off <<= 1) {
        int v = (t >= off) ? sh[t - off] : 0;
        __syncthreads();
        sh[t] += v;
        __syncthreads();
    }
    int run = (t > 0) ? sh[t - 1] : 0;
    for (int k = 0; k < C; ++k) {
        int i = t * C + k;
        if (i < kNodes) {
            g_offs[i]   = run;
            g_cursor[i] = run;
            run += g_count[i];
        }
    }
    if (t == T - 1) g_offs[kNodes] = sh[T - 1];
}

__global__ void scatter_kernel(const void* __restrict__ ei) {
    int e = blockIdx.x * blockDim.x + threadIdx.x;
    if (e >= kEdges) return;
    int s = load_idx(ei, e);
    int g = load_idx(ei, (long long)kEdges + e);
    int pos = atomicAdd(&g_cursor[g], 1);
    g_srcs[pos] = s;
}

// ---- compute ----

// xc = l2norm_per_capsule(x). One warp per node, float4 per lane.
__global__ void __launch_bounds__(256) init_kernel(const float* __restrict__ x) {
    int gid  = blockIdx.x * blockDim.x + threadIdx.x;
    int node = gid >> 5;
    if (node >= kNodes) return;
    int t   = gid & 31;
    int idx = node * 32 + t;

    float4 v = reinterpret_cast<const float4*>(x)[idx];
    float ss = group4_sum(v.x * v.x + v.y * v.y + v.z * v.z + v.w * v.w);
    float s  = 1.0f / fmaxf(sqrtf(ss), 1e-12f);
    v.x *= s; v.y *= s; v.z *= s; v.w *= s;
    g_xc[idx] = v;
}

// One full routing iteration fused per node: warp n owns target node n.
// Lane t holds float4 #t of the 128-float row; capsule of lane t = t>>2.
// Softmax over 8 caps needs no max-subtract: capsules are unit vectors => p in [-1,1].
template <bool FIRST, bool WRITE_OUT>
__global__ void __launch_bounds__(256) route_kernel(float* __restrict__ out) {
    int gid  = blockIdx.x * blockDim.x + threadIdx.x;
    int node = gid >> 5;
    if (node >= kNodes) return;
    int t   = gid & 31;
    int idx = node * 32 + t;

    float4 c = g_xc[idx];
    float4 u = FIRST ? c : g_u[idx];

    int beg = g_offs[node];
    int end = g_offs[node + 1];

    float4 acc = make_float4(0.f, 0.f, 0.f, 0.f);
    int i = beg;
    for (; i + 2 <= end; i += 2) {
        int s0 = g_srcs[i];
        int s1 = g_srcs[i + 1];
        float4 z0 = g_xc[s0 * 32 + t];
        float4 z1 = g_xc[s1 * 32 + t];

        float p0 = group4_sum(z0.x * u.x + z0.y * u.y + z0.z * u.z + z0.w * u.w);
        float p1 = group4_sum(z1.x * u.x + z1.y * u.y + z1.z * u.z + z1.w * u.w);
        float e0 = __expf(p0);
        float e1 = __expf(p1);
        float q0 = e0, q1 = e1;
        q0 += __shfl_xor_sync(0xffffffffu, q0, 4);
        q1 += __shfl_xor_sync(0xffffffffu, q1, 4);
        q0 += __shfl_xor_sync(0xffffffffu, q0, 8);
        q1 += __shfl_xor_sync(0xffffffffu, q1, 8);
        q0 += __shfl_xor_sync(0xffffffffu, q0, 16);
        q1 += __shfl_xor_sync(0xffffffffu, q1, 16);
        float w0 = __fdividef(e0, q0);
        float w1 = __fdividef(e1, q1);

        acc.x += z0.x * w0 + z1.x * w1;
        acc.y += z0.y * w0 + z1.y * w1;
        acc.z += z0.z * w0 + z1.z * w1;
        acc.w += z0.w * w0 + z1.w * w1;
    }
    if (i < end) {
        int s0 = g_srcs[i];
        float4 z0 = g_xc[s0 * 32 + t];
        float p0 = group4_sum(z0.x * u.x + z0.y * u.y + z0.z * u.z + z0.w * u.w);
        float e0 = __expf(p0);
        float q0 = e0;
        q0 += __shfl_xor_sync(0xffffffffu, q0, 4);
        q0 += __shfl_xor_sync(0xffffffffu, q0, 8);
        q0 += __shfl_xor_sync(0xffffffffu, q0, 16);
        float w0 = __fdividef(e0, q0);
        acc.x += z0.x * w0;
        acc.y += z0.y * w0;
        acc.z += z0.z * w0;
        acc.w += z0.w * w0;
    }

    // u_new = l2norm_per_capsule(acc + xc); only this warp touches row `node`.
    float4 v = make_float4(acc.x + c.x, acc.y + c.y, acc.z + c.z, acc.w + c.w);
    float ss = group4_sum(v.x * v.x + v.y * v.y + v.z * v.z + v.w * v.w);
    float s  = 1.0f / fmaxf(sqrtf(ss), 1e-12f);
    v.x *= s; v.y *= s; v.z *= s; v.w *= s;

    if (WRITE_OUT) {
        reinterpret_cast<float4*>(out)[idx] = v;
    } else {
        g_u[idx] = v;
    }
}

}  // namespace

extern "C" void kernel_launch(void* const* d_in, const int* in_sizes, int n_in,
                              void* d_out, int out_size) {
    const float* x  = (const float*)d_in[0];
    const void*  ei = d_in[1];   // [2, E], int32 or int64 (detected on-device)
    float* out = (float*)d_out;

    const int nodeBlocks = (kNodes * 32 + 255) / 256;
    const int edgeBlocks = (kEdges + 255) / 256;

    detect_kernel<<<1, 32>>>((const unsigned int*)ei);
    zero_count_kernel<<<(kNodes + 256) / 256, 256>>>();
    hist_kernel<<<edgeBlocks, 256>>>(ei);
    scan_kernel<<<1, 1024>>>();
    scatter_kernel<<<edgeBlocks, 256>>>(ei);
    init_kernel<<<nodeBlocks, 256>>>(x);

    route_kernel<true,  false><<<nodeBlocks, 256>>>(nullptr);
    route_kernel<false, false><<<nodeBlocks, 256>>>(nullptr);
    route_kernel<false, true ><<<nodeBlocks, 256>>>(out);
}

// round 5
// speedup vs baseline: 2.2304x; 2.0862x over previous
#include <cuda_runtime.h>

namespace {

constexpr int kNodes = 50000;
constexpr int kEdges = 800000;
constexpr int kScanBlocks = (kNodes + 255) / 256;  // 196

// Scratch (allocation-free __device__ globals; float4-typed => 16B aligned).
__device__ float4 g_xc[kNodes * 32];   // per-capsule-normalized input
__device__ float4 g_u [kNodes * 32];   // routing state (updated in place per node)
__device__ int    g_count [kNodes + 1];
__device__ int    g_incl  [kNodes + 1];  // per-block inclusive scan values
__device__ int    g_bsum  [kScanBlocks]; // per-block totals
__device__ int    g_bpre  [kScanBlocks]; // exclusive prefix of block totals
__device__ int    g_offs  [kNodes + 1];  // CSR row offsets (by target)
__device__ int    g_cursor[kNodes];
__device__ int    g_srcs  [kEdges];      // CSR column (source node per edge)
__device__ int    g_is_i32;              // edge_index dtype flag

__device__ __forceinline__ float group4_sum(float v) {
    v += __shfl_xor_sync(0xffffffffu, v, 1);
    v += __shfl_xor_sync(0xffffffffu, v, 2);
    return v;
}

__device__ __forceinline__ int load_idx(const void* ei, long long off) {
    if (g_is_i32) return ((const int*)ei)[off];
    return (int)((const long long*)ei)[off];
}

// ---- preprocessing: dtype detect + counting sort of edges by target ----

__global__ void detect_kernel(const unsigned int* __restrict__ w) {
    unsigned int acc = 0;
    for (int i = threadIdx.x; i < 1024; i += 32) acc |= w[2 * i + 1];
    #pragma unroll
    for (int d = 1; d < 32; d <<= 1) acc |= __shfl_xor_sync(0xffffffffu, acc, d);
    if (threadIdx.x == 0) g_is_i32 = (acc != 0) ? 1 : 0;
}

__global__ void zero_count_kernel() {
    int i = blockIdx.x * blockDim.x + threadIdx.x;
    if (i <= kNodes) g_count[i] = 0;
}

__global__ void hist_kernel(const void* __restrict__ ei) {
    int e = blockIdx.x * blockDim.x + threadIdx.x;
    if (e >= kEdges) return;
    atomicAdd(&g_count[load_idx(ei, (long long)kEdges + e)], 1);
}

// S1: per-block inclusive scan of counts (256/block) + block totals.
__global__ void __launch_bounds__(256) scan1_kernel() {
    __shared__ int warp_tot[8];
    int i    = blockIdx.x * 256 + threadIdx.x;
    int lane = threadIdx.x & 31;
    int wid  = threadIdx.x >> 5;

    int v = (i < kNodes) ? g_count[i] : 0;
    int x = v;
    #pragma unroll
    for (int d = 1; d < 32; d <<= 1) {
        int y = __shfl_up_sync(0xffffffffu, x, d);
        if (lane >= d) x += y;
    }
    if (lane == 31) warp_tot[wid] = x;
    __syncthreads();
    if (wid == 0) {
        int t = (lane < 8) ? warp_tot[lane] : 0;
        #pragma unroll
        for (int d = 1; d < 8; d <<= 1) {
            int y = __shfl_up_sync(0xffffffffu, t, d);
            if (lane >= d) t += y;
        }
        if (lane < 8) warp_tot[lane] = t;
    }
    __syncthreads();
    int incl = x + (wid > 0 ? warp_tot[wid - 1] : 0);
    if (i < kNodes) g_incl[i] = incl;
    if (threadIdx.x == 255) g_bsum[blockIdx.x] = incl;
}

// S2: exclusive scan of 196 block totals (single tiny block).
__global__ void __launch_bounds__(256) scan2_kernel() {
    __shared__ int warp_tot[8];
    int lane = threadIdx.x & 31;
    int wid  = threadIdx.x >> 5;
    int v = (threadIdx.x < kScanBlocks) ? g_bsum[threadIdx.x] : 0;
    int x = v;
    #pragma unroll
    for (int d = 1; d < 32; d <<= 1) {
        int y = __shfl_up_sync(0xffffffffu, x, d);
        if (lane >= d) x += y;
    }
    if (lane == 31) warp_tot[wid] = x;
    __syncthreads();
    if (wid == 0) {
        int t = (lane < 8) ? warp_tot[lane] : 0;
        #pragma unroll
        for (int d = 1; d < 8; d <<= 1) {
            int y = __shfl_up_sync(0xffffffffu, t, d);
            if (lane >= d) t += y;
        }
        if (lane < 8) warp_tot[lane] = t;
    }
    __syncthreads();
    int incl = x + (wid > 0 ? warp_tot[wid - 1] : 0);
    if (threadIdx.x < kScanBlocks) g_bpre[threadIdx.x] = incl - v;  // exclusive
}

// S3: offs[i] = bpre[blk] + incl[i] - count[i]; cursor = offs; offs[N] = E.
__global__ void __launch_bounds__(256) scan3_kernel() {
    int i = blockIdx.x * 256 + threadIdx.x;
    if (i < kNodes) {
        int off = g_bpre[blockIdx.x] + g_incl[i] - g_count[i];
        g_offs[i]   = off;
        g_cursor[i] = off;
    }
    if (i == 0) g_offs[kNodes] = kEdges;
}

__global__ void scatter_kernel(const void* __restrict__ ei) {
    int e = blockIdx.x * blockDim.x + threadIdx.x;
    if (e >= kEdges) return;
    int s = load_idx(ei, e);
    int g = load_idx(ei, (long long)kEdges + e);
    int pos = atomicAdd(&g_cursor[g], 1);
    g_srcs[pos] = s;
}

// ---- compute ----

// xc = l2norm_per_capsule(x). One warp per node, float4 per lane.
__global__ void __launch_bounds__(256) init_kernel(const float* __restrict__ x) {
    int gid  = blockIdx.x * blockDim.x + threadIdx.x;
    int node = gid >> 5;
    if (node >= kNodes) return;
    int t   = gid & 31;
    int idx = node * 32 + t;

    float4 v = reinterpret_cast<const float4*>(x)[idx];
    float ss = group4_sum(v.x * v.x + v.y * v.y + v.z * v.z + v.w * v.w);
    float s  = 1.0f / fmaxf(sqrtf(ss), 1e-12f);
    v.x *= s; v.y *= s; v.z *= s; v.w *= s;
    g_xc[idx] = v;
}

// One full routing iteration fused per node: warp n owns target node n.
// Lane t holds float4 #t of the 128-float row; capsule of lane t = t>>2.
// Softmax needs no max-subtract: capsules are unit vectors => p in [-1,1].
template <bool FIRST, bool WRITE_OUT>
__global__ void __launch_bounds__(256) route_kernel(float* __restrict__ out) {
    int gid  = blockIdx.x * blockDim.x + threadIdx.x;
    int node = gid >> 5;
    if (node >= kNodes) return;
    int t   = gid & 31;
    int idx = node * 32 + t;

    float4 c = g_xc[idx];
    float4 u = FIRST ? c : g_u[idx];

    int beg = g_offs[node];
    int end = g_offs[node + 1];

    float4 acc = make_float4(0.f, 0.f, 0.f, 0.f);
    int i = beg;
    for (; i + 2 <= end; i += 2) {
        int s0 = g_srcs[i];
        int s1 = g_srcs[i + 1];
        float4 z0 = g_xc[s0 * 32 + t];
        float4 z1 = g_xc[s1 * 32 + t];

        float p0 = group4_sum(z0.x * u.x + z0.y * u.y + z0.z * u.z + z0.w * u.w);
        float p1 = group4_sum(z1.x * u.x + z1.y * u.y + z1.z * u.z + z1.w * u.w);
        float e0 = __expf(p0);
        float e1 = __expf(p1);
        float q0 = e0, q1 = e1;
        q0 += __shfl_xor_sync(0xffffffffu, q0, 4);
        q1 += __shfl_xor_sync(0xffffffffu, q1, 4);
        q0 += __shfl_xor_sync(0xffffffffu, q0, 8);
        q1 += __shfl_xor_sync(0xffffffffu, q1, 8);
        q0 += __shfl_xor_sync(0xffffffffu, q0, 16);
        q1 += __shfl_xor_sync(0xffffffffu, q1, 16);
        float w0 = __fdividef(e0, q0);
        float w1 = __fdividef(e1, q1);

        acc.x += z0.x * w0 + z1.x * w1;
        acc.y += z0.y * w0 + z1.y * w1;
        acc.z += z0.z * w0 + z1.z * w1;
        acc.w += z0.w * w0 + z1.w * w1;
    }
    if (i < end) {
        int s0 = g_srcs[i];
        float4 z0 = g_xc[s0 * 32 + t];
        float p0 = group4_sum(z0.x * u.x + z0.y * u.y + z0.z * u.z + z0.w * u.w);
        float e0 = __expf(p0);
        float q0 = e0;
        q0 += __shfl_xor_sync(0xffffffffu, q0, 4);
        q0 += __shfl_xor_sync(0xffffffffu, q0, 8);
        q0 += __shfl_xor_sync(0xffffffffu, q0, 16);
        float w0 = __fdividef(e0, q0);
        acc.x += z0.x * w0;
        acc.y += z0.y * w0;
        acc.z += z0.z * w0;
        acc.w += z0.w * w0;
    }

    // u_new = l2norm_per_capsule(acc + xc); only this warp touches row `node`.
    float4 v = make_float4(acc.x + c.x, acc.y + c.y, acc.z + c.z, acc.w + c.w);
    float ss = group4_sum(v.x * v.x + v.y * v.y + v.z * v.z + v.w * v.w);
    float s  = 1.0f / fmaxf(sqrtf(ss), 1e-12f);
    v.x *= s; v.y *= s; v.z *= s; v.w *= s;

    if (WRITE_OUT) {
        reinterpret_cast<float4*>(out)[idx] = v;
    } else {
        g_u[idx] = v;
    }
}

}  // namespace

extern "C" void kernel_launch(void* const* d_in, const int* in_sizes, int n_in,
                              void* d_out, int out_size) {
    const float* x  = (const float*)d_in[0];
    const void*  ei = d_in[1];   // [2, E], int32 or int64 (detected on-device)
    float* out = (float*)d_out;

    const int nodeBlocks = (kNodes * 32 + 255) / 256;
    const int edgeBlocks = (kEdges + 255) / 256;

    detect_kernel<<<1, 32>>>((const unsigned int*)ei);
    zero_count_kernel<<<(kNodes + 256) / 256, 256>>>();
    hist_kernel<<<edgeBlocks, 256>>>(ei);
    scan1_kernel<<<kScanBlocks, 256>>>();
    scan2_kernel<<<1, 256>>>();
    scan3_kernel<<<kScanBlocks, 256>>>();
    scatter_kernel<<<edgeBlocks, 256>>>(ei);
    init_kernel<<<nodeBlocks, 256>>>(x);

    route_kernel<true,  false><<<nodeBlocks, 256>>>(nullptr);
    route_kernel<false, false><<<nodeBlocks, 256>>>(nullptr);
    route_kernel<false, true ><<<nodeBlocks, 256>>>(out);
}

// round 7
// speedup vs baseline: 2.2853x; 1.0246x over previous
#include <cuda_runtime.h>
#include <cuda_fp16.h>

namespace {

constexpr int kNodes = 50000;
constexpr int kEdges = 800000;
constexpr int kScanBlocks = (kNodes + 255) / 256;  // 196

// Scratch (allocation-free __device__ globals; 16B-aligned types where needed).
__device__ float4 g_xc [kNodes * 32];  // fp32 normalized caps (residual + norm path)
__device__ uint2  g_xch[kNodes * 32];  // fp16 copy: lane t's 4 dims as 2x half2
__device__ float4 g_u  [kNodes * 32];  // routing state (updated in place per node)
__device__ int    g_count [kNodes + 1];
__device__ int    g_incl  [kNodes + 1];
__device__ int    g_bsum  [kScanBlocks];
__device__ int    g_bpre  [kScanBlocks];
__device__ int    g_offs  [kNodes + 1];  // CSR row offsets (by target)
__device__ int    g_cursor[kNodes];
__device__ int    g_srcs  [kEdges];      // CSR column (source node per edge)
__device__ int    g_is_i32;              // edge_index dtype flag

__device__ __forceinline__ float group4_sum(float v) {
    v += __shfl_xor_sync(0xffffffffu, v, 1);
    v += __shfl_xor_sync(0xffffffffu, v, 2);
    return v;
}

__device__ __forceinline__ int load_idx(const void* ei, long long off) {
    if (g_is_i32) return ((const int*)ei)[off];
    return (int)((const long long*)ei)[off];
}

__device__ __forceinline__ float4 load_z_h(int idx) {
    uint2 w = g_xch[idx];
    float2 a = __half22float2(*reinterpret_cast<const half2*>(&w.x));
    float2 b = __half22float2(*reinterpret_cast<const half2*>(&w.y));
    return make_float4(a.x, a.y, b.x, b.y);
}

// ---- preprocessing: dtype detect + counting sort of edges by target ----

__global__ void detect_kernel(const unsigned int* __restrict__ w) {
    unsigned int acc = 0;
    for (int i = threadIdx.x; i < 1024; i += 32) acc |= w[2 * i + 1];
    #pragma unroll
    for (int d = 1; d < 32; d <<= 1) acc |= __shfl_xor_sync(0xffffffffu, acc, d);
    if (threadIdx.x == 0) g_is_i32 = (acc != 0) ? 1 : 0;
}

__global__ void zero_count_kernel() {
    int i = blockIdx.x * blockDim.x + threadIdx.x;
    if (i <= kNodes) g_count[i] = 0;
}

__global__ void hist_kernel(const void* __restrict__ ei) {
    int e = blockIdx.x * blockDim.x + threadIdx.x;
    if (e >= kEdges) return;
    atomicAdd(&g_count[load_idx(ei, (long long)kEdges + e)], 1);
}

// S1: per-block inclusive scan of counts (256/block) + block totals.
__global__ void __launch_bounds__(256) scan1_kernel() {
    __shared__ int warp_tot[8];
    int i    = blockIdx.x * 256 + threadIdx.x;
    int lane = threadIdx.x & 31;
    int wid  = threadIdx.x >> 5;

    int v = (i < kNodes) ? g_count[i] : 0;
    int x = v;
    #pragma unroll
    for (int d = 1; d < 32; d <<= 1) {
        int y = __shfl_up_sync(0xffffffffu, x, d);
        if (lane >= d) x += y;
    }
    if (lane == 31) warp_tot[wid] = x;
    __syncthreads();
    if (wid == 0) {
        int t = (lane < 8) ? warp_tot[lane] : 0;
        #pragma unroll
        for (int d = 1; d < 8; d <<= 1) {
            int y = __shfl_up_sync(0xffffffffu, t, d);
            if (lane >= d) t += y;
        }
        if (lane < 8) warp_tot[lane] = t;
    }
    __syncthreads();
    int incl = x + (wid > 0 ? warp_tot[wid - 1] : 0);
    if (i < kNodes) g_incl[i] = incl;
    if (threadIdx.x == 255) g_bsum[blockIdx.x] = incl;
}

// S2: exclusive scan of 196 block totals (single tiny block).
__global__ void __launch_bounds__(256) scan2_kernel() {
    __shared__ int warp_tot[8];
    int lane = threadIdx.x & 31;
    int wid  = threadIdx.x >> 5;
    int v = (threadIdx.x < kScanBlocks) ? g_bsum[threadIdx.x] : 0;
    int x = v;
    #pragma unroll
    for (int d = 1; d < 32; d <<= 1) {
        int y = __shfl_up_sync(0xffffffffu, x, d);
        if (lane >= d) x += y;
    }
    if (lane == 31) warp_tot[wid] = x;
    __syncthreads();
    if (wid == 0) {
        int t = (lane < 8) ? warp_tot[lane] : 0;
        #pragma unroll
        for (int d = 1; d < 8; d <<= 1) {
            int y = __shfl_up_sync(0xffffffffu, t, d);
            if (lane >= d) t += y;
        }
        if (lane < 8) warp_tot[lane] = t;
    }
    __syncthreads();
    int incl = x + (wid > 0 ? warp_tot[wid - 1] : 0);
    if (threadIdx.x < kScanBlocks) g_bpre[threadIdx.x] = incl - v;  // exclusive
}

// S3: offs[i] = bpre[blk] + incl[i] - count[i]; cursor = offs; offs[N] = E.
__global__ void __launch_bounds__(256) scan3_kernel() {
    int i = blockIdx.x * 256 + threadIdx.x;
    if (i < kNodes) {
        int off = g_bpre[blockIdx.x] + g_incl[i] - g_count[i];
        g_offs[i]   = off;
        g_cursor[i] = off;
    }
    if (i == 0) g_offs[kNodes] = kEdges;
}

__global__ void scatter_kernel(const void* __restrict__ ei) {
    int e = blockIdx.x * blockDim.x + threadIdx.x;
    if (e >= kEdges) return;
    int s = load_idx(ei, e);
    int g = load_idx(ei, (long long)kEdges + e);
    int pos = atomicAdd(&g_cursor[g], 1);
    g_srcs[pos] = s;
}

// ---- compute ----

// xc = l2norm_per_capsule(x); write fp32 + fp16 copies. One warp per node.
__global__ void __launch_bounds__(256) init_kernel(const float* __restrict__ x) {
    int gid  = blockIdx.x * blockDim.x + threadIdx.x;
    int node = gid >> 5;
    if (node >= kNodes) return;
    int t   = gid & 31;
    int idx = node * 32 + t;

    float4 v = reinterpret_cast<const float4*>(x)[idx];
    float ss = group4_sum(v.x * v.x + v.y * v.y + v.z * v.z + v.w * v.w);
    float s  = 1.0f / fmaxf(sqrtf(ss), 1e-12f);
    v.x *= s; v.y *= s; v.z *= s; v.w *= s;
    g_xc[idx] = v;

    half2 a = __floats2half2_rn(v.x, v.y);
    half2 b = __floats2half2_rn(v.z, v.w);
    uint2 w;
    w.x = *reinterpret_cast<const unsigned int*>(&a);
    w.y = *reinterpret_cast<const unsigned int*>(&b);
    g_xch[idx] = w;
}

// One full routing iteration fused per node: warp n owns target node n.
// Lane t holds dims [4t,4t+4); capsule of lane t = t>>2.
// z gathered in fp16 (halved L2 traffic); residual/norm in fp32.
// Softmax needs no max-subtract: capsules are unit vectors => p in [-1,1].
template <bool FIRST, bool WRITE_OUT>
__global__ void __launch_bounds__(256) route_kernel(float* __restrict__ out) {
    int gid  = blockIdx.x * blockDim.x + threadIdx.x;
    int node = gid >> 5;
    if (node >= kNodes) return;
    int t   = gid & 31;
    int idx = node * 32 + t;

    float4 c = g_xc[idx];
    float4 u = FIRST ? c : g_u[idx];

    int beg = g_offs[node];
    int end = g_offs[node + 1];

    float4 acc = make_float4(0.f, 0.f, 0.f, 0.f);
    int i = beg;
    for (; i + 2 <= end; i += 2) {
        int s0 = g_srcs[i];
        int s1 = g_srcs[i + 1];
        float4 z0 = load_z_h(s0 * 32 + t);
        float4 z1 = load_z_h(s1 * 32 + t);

        float p0 = group4_sum(z0.x * u.x + z0.y * u.y + z0.z * u.z + z0.w * u.w);
        float p1 = group4_sum(z1.x * u.x + z1.y * u.y + z1.z * u.z + z1.w * u.w);
        float e0 = __expf(p0);
        float e1 = __expf(p1);
        float q0 = e0, q1 = e1;
        q0 += __shfl_xor_sync(0xffffffffu, q0, 4);
        q1 += __shfl_xor_sync(0xffffffffu, q1, 4);
        q0 += __shfl_xor_sync(0xffffffffu, q0, 8);
        q1 += __shfl_xor_sync(0xffffffffu, q1, 8);
        q0 += __shfl_xor_sync(0xffffffffu, q0, 16);
        q1 += __shfl_xor_sync(0xffffffffu, q1, 16);
        float w0 = __fdividef(e0, q0);
        float w1 = __fdividef(e1, q1);

        acc.x += z0.x * w0 + z1.x * w1;
        acc.y += z0.y * w0 + z1.y * w1;
        acc.z += z0.z * w0 + z1.z * w1;
        acc.w += z0.w * w0 + z1.w * w1;
    }
    if (i < end) {
        int s0 = g_srcs[i];
        float4 z0 = load_z_h(s0 * 32 + t);
        float p0 = group4_sum(z0.x * u.x + z0.y * u.y + z0.z * u.z + z0.w * u.w);
        float e0 = __expf(p0);
        float q0 = e0;
        q0 += __shfl_xor_sync(0xffffffffu, q0, 4);
        q0 += __shfl_xor_sync(0xffffffffu, q0, 8);
        q0 += __shfl_xor_sync(0xffffffffu, q0, 16);
        float w0 = __fdividef(e0, q0);
        acc.x += z0.x * w0;
        acc.y += z0.y * w0;
        acc.z += z0.z * w0;
        acc.w += z0.w * w0;
    }

    // u_new = l2norm_per_capsule(acc + xc); only this warp touches row `node`.
    float4 v = make_float4(acc.x + c.x, acc.y + c.y, acc.z + c.z, acc.w + c.w);
    float ss = group4_sum(v.x * v.x + v.y * v.y + v.z * v.z + v.w * v.w);
    float s  = 1.0f / fmaxf(sqrtf(ss), 1e-12f);
    v.x *= s; v.y *= s; v.z *= s; v.w *= s;

    if (WRITE_OUT) {
        reinterpret_cast<float4*>(out)[idx] = v;
    } else {
        g_u[idx] = v;
    }
}

}  // namespace

extern "C" void kernel_launch(void* const* d_in, const int* in_sizes, int n_in,
                              void* d_out, int out_size) {
    const float* x  = (const float*)d_in[0];
    const void*  ei = d_in[1];   // [2, E], int32 or int64 (detected on-device)
    float* out = (float*)d_out;

    const int nodeBlocks = (kNodes * 32 + 255) / 256;
    const int edgeBlocks = (kEdges + 255) / 256;

    detect_kernel<<<1, 32>>>((const unsigned int*)ei);
    zero_count_kernel<<<(kNodes + 256) / 256, 256>>>();
    hist_kernel<<<edgeBlocks, 256>>>(ei);
    scan1_kernel<<<kScanBlocks, 256>>>();
    scan2_kernel<<<1, 256>>>();
    scan3_kernel<<<kScanBlocks, 256>>>();
    scatter_kernel<<<edgeBlocks, 256>>>(ei);
    init_kernel<<<nodeBlocks, 256>>>(x);

    route_kernel<true,  false><<<nodeBlocks, 256>>>(nullptr);
    route_kernel<false, false><<<nodeBlocks, 256>>>(nullptr);
    route_kernel<false, true ><<<nodeBlocks, 256>>>(out);
}